// round 1
// baseline (speedup 1.0000x reference)
#include <cuda_runtime.h>
#include <cuda_bf16.h>
#include <cstdint>

// Problem constants
#define NN   16384      // nodes
#define KK   16         // clusters
// adj: [NN, NN] f32 (1 GiB), C: [NN, KK] f32, X unused, beta scalar.
//
// Decomposition (single streaming pass over adj):
//   sumA   = sum_ij A_ij                       -> m = sumA/2
//   dC[k]  = sum_ij A_ij * C[i,k]
//   term1  = sum_ij A_ij * <C_i, C_j>
//   colsum[k] = sum_i C[i,k]
// final: out = -(term1 - dot(dC,dC)/(2m))/(2m) + beta * (sqrt(K)/N)*sum|colsum-1|

typedef unsigned long long u64;

__device__ __forceinline__ u64 pk2(float lo, float hi) {
    u64 r; asm("mov.b64 %0, {%1, %2};" : "=l"(r) : "f"(lo), "f"(hi)); return r;
}
__device__ __forceinline__ void unpk2(u64 v, float &lo, float &hi) {
    asm("mov.b64 {%0, %1}, %2;" : "=f"(lo), "=f"(hi) : "l"(v));
}
__device__ __forceinline__ u64 mul2(u64 a, u64 b) {
    u64 d; asm("mul.rn.f32x2 %0, %1, %2;" : "=l"(d) : "l"(a), "l"(b)); return d;
}
__device__ __forceinline__ void fma2(u64 &d, u64 a, u64 b) {
    asm("fma.rn.f32x2 %0, %1, %2, %0;" : "+l"(d) : "l"(a), "l"(b));
}

// Global accumulators: [0]=term1, [1]=sumA, [2..17]=dC[16], [18..33]=colsum[16]
__device__ double g_acc[34];

__global__ void init_acc() {
    int t = threadIdx.x;
    if (t < 34) g_acc[t] = 0.0;
}

// Grid: (16 column-slabs, 64 row-groups). Block: 256 threads.
// Each thread owns 4 consecutive columns j (one float4 of each adj row),
// holds C[j0..j0+3][0..15] in registers (packed f32x2), and iterates over
// the block's 256 rows i.
__global__ void __launch_bounds__(256)
mod_main(const float4 * __restrict__ adj4, const float * __restrict__ C)
{
    const int tid  = threadIdx.x;
    const int slab = blockIdx.x;   // 0..15 (1024 columns each)
    const int grp  = blockIdx.y;   // 0..63 (256 rows each)
    const int i0   = grp * 256;
    const int jb   = slab * 1024 + tid * 4;   // first column owned

    // ---- load C[jb..jb+3][*] into registers, packed as f32x2 pairs ----
    u64 c[4][8];
    {
        const float4 *Cf4 = reinterpret_cast<const float4 *>(C);
        #pragma unroll
        for (int t = 0; t < 4; t++) {
            #pragma unroll
            for (int q = 0; q < 4; q++) {
                float4 w = Cf4[(size_t)(jb + t) * 4 + q];
                c[t][2 * q]     = pk2(w.x, w.y);
                c[t][2 * q + 1] = pk2(w.z, w.w);
            }
        }
    }

    u64 dc[8], tacc[4];
    #pragma unroll
    for (int r = 0; r < 8; r++) dc[r] = pk2(0.f, 0.f);
    #pragma unroll
    for (int r = 0; r < 4; r++) tacc[r] = pk2(0.f, 0.f);
    float macc = 0.f;

    const float4 *arow = adj4 + (size_t)i0 * 4096 + (size_t)(slab * 256 + tid);
    const float4 *Cf4  = reinterpret_cast<const float4 *>(C);

    // prefetch ring, depth 4
    float4 a[4];
    #pragma unroll
    for (int u = 0; u < 4; u++) a[u] = arow[(size_t)u * 4096];

    for (int ii = 0; ii < 256; ii += 4) {
        #pragma unroll
        for (int u = 0; u < 4; u++) {
            float4 av = a[u];
            int nxt = ii + 4 + u;
            if (nxt < 256) a[u] = arow[(size_t)nxt * 4096];

            const int i = i0 + ii + u;
            // C_i: 4x LDG.128, same address across warp -> L1 broadcast
            u64 ci[8];
            #pragma unroll
            for (int q = 0; q < 4; q++) {
                float4 w = Cf4[(size_t)i * 4 + q];
                ci[2 * q]     = pk2(w.x, w.y);
                ci[2 * q + 1] = pk2(w.z, w.w);
            }

            u64 ax = pk2(av.x, av.x), ay = pk2(av.y, av.y);
            u64 az = pk2(av.z, av.z), aw = pk2(av.w, av.w);

            u64 p[8];
            #pragma unroll
            for (int r = 0; r < 8; r++) p[r] = mul2(ax, c[0][r]);
            #pragma unroll
            for (int r = 0; r < 8; r++) fma2(p[r], ay, c[1][r]);
            #pragma unroll
            for (int r = 0; r < 8; r++) fma2(p[r], az, c[2][r]);
            #pragma unroll
            for (int r = 0; r < 8; r++) fma2(p[r], aw, c[3][r]);

            // term1 partial: tacc += p .* C_i   (4 independent accumulators)
            #pragma unroll
            for (int r = 0; r < 8; r++) fma2(tacc[r & 3], p[r], ci[r]);

            // row-sum of this thread's 4 adj elements
            float sv = (av.x + av.y) + (av.z + av.w);
            macc += sv;
            u64 s2 = pk2(sv, sv);
            // dC partial: dc += s * C_i
            #pragma unroll
            for (int r = 0; r < 8; r++) fma2(dc[r], s2, ci[r]);
        }
    }

    // colsum: computed once (slab 0 only), one row per thread
    float cs[16];
    #pragma unroll
    for (int k = 0; k < 16; k++) cs[k] = 0.f;
    if (slab == 0) {
        const int irow = i0 + tid;   // 256 rows per block, 256 threads
        #pragma unroll
        for (int q = 0; q < 4; q++) {
            float4 w = Cf4[(size_t)irow * 4 + q];
            cs[4 * q + 0] = w.x; cs[4 * q + 1] = w.y;
            cs[4 * q + 2] = w.z; cs[4 * q + 3] = w.w;
        }
    }

    // ---- block reduction of 34 quantities ----
    float vals[34];
    {
        float t1 = 0.f;
        #pragma unroll
        for (int r = 0; r < 4; r++) { float lo, hi; unpk2(tacc[r], lo, hi); t1 += lo + hi; }
        vals[0] = t1;
        vals[1] = macc;
        #pragma unroll
        for (int r = 0; r < 8; r++) {
            float lo, hi; unpk2(dc[r], lo, hi);
            vals[2 + 2 * r] = lo; vals[3 + 2 * r] = hi;
        }
        #pragma unroll
        for (int k = 0; k < 16; k++) vals[18 + k] = cs[k];
    }

    __shared__ float red[8][34];
    const int lane = tid & 31, warp = tid >> 5;
    #pragma unroll
    for (int q = 0; q < 34; q++) {
        float v = vals[q];
        #pragma unroll
        for (int off = 16; off > 0; off >>= 1)
            v += __shfl_down_sync(0xFFFFFFFFu, v, off);
        if (lane == 0) red[warp][q] = v;
    }
    __syncthreads();
    if (tid < 34) {
        double s = 0.0;
        #pragma unroll
        for (int w = 0; w < 8; w++) s += (double)red[w][tid];
        atomicAdd(&g_acc[tid], s);
    }
}

__global__ void mod_final(const float * __restrict__ beta, float * __restrict__ out)
{
    if (threadIdx.x != 0) return;
    double term1 = g_acc[0];
    double sumA  = g_acc[1];
    double m     = sumA * 0.5;
    double two_m = 2.0 * m;
    double dot = 0.0;
    #pragma unroll
    for (int k = 0; k < 16; k++) { double d = g_acc[2 + k]; dot += d * d; }
    double modularity_term = term1 - dot / two_m;
    double mod_loss = -modularity_term / two_m;
    double col = 0.0;
    #pragma unroll
    for (int k = 0; k < 16; k++) col += fabs(g_acc[18 + k] - 1.0);
    double collapse = (4.0 / (double)NN) * col;   // sqrt(16)=4
    out[0] = (float)(mod_loss + (double)beta[0] * collapse);
}

extern "C" void kernel_launch(void* const* d_in, const int* in_sizes, int n_in,
                              void* d_out, int out_size)
{
    const float *C    = (const float *)d_in[0];
    // d_in[1] = X, unused by the loss
    const float *adj  = (const float *)d_in[2];
    const float *beta = (const float *)d_in[3];
    float *out = (float *)d_out;
    (void)in_sizes; (void)n_in; (void)out_size;

    init_acc<<<1, 64>>>();
    mod_main<<<dim3(16, 64), 256>>>((const float4 *)adj, C);
    mod_final<<<1, 32>>>(beta, out);
}

// round 2
// speedup vs baseline: 3.3128x; 3.3128x over previous
#include <cuda_runtime.h>
#include <cuda_bf16.h>
#include <cstdint>

// Problem: modularity loss over adj[16384,16384] f32 (1 GiB streamed once).
//   sumA   = sum_ij A_ij                     -> m = sumA/2
//   dC[k]  = sum_i (rowsum_i) * C[i,k]
//   term1  = sum_i <C_i, sum_j A_ij C_j>
//   colsum[k] = sum_i C[i,k]
// out = -(term1 - dot(dC,dC)/(2m))/(2m) + beta * (sqrt(K)/N) * sum|colsum-1|

#define NN 16384
#define RR 256          // rows per block

typedef unsigned long long u64;

__device__ __forceinline__ u64 pk2(float lo, float hi) {
    u64 r; asm("mov.b64 %0, {%1, %2};" : "=l"(r) : "f"(lo), "f"(hi)); return r;
}
__device__ __forceinline__ void unpk2(u64 v, float &lo, float &hi) {
    asm("mov.b64 {%0, %1}, %2;" : "=f"(lo), "=f"(hi) : "l"(v));
}
__device__ __forceinline__ u64 mul2(u64 a, u64 b) {
    u64 d; asm("mul.rn.f32x2 %0, %1, %2;" : "=l"(d) : "l"(a), "l"(b)); return d;
}
__device__ __forceinline__ void fma2(u64 &d, u64 a, u64 b) {
    asm("fma.rn.f32x2 %0, %1, %2, %0;" : "+l"(d) : "l"(a), "l"(b));
}

// [0]=term1, [1]=sumA, [2..17]=dC, [18..33]=colsum
__device__ double g_acc[34];

__global__ void init_acc() {
    int t = threadIdx.x;
    if (t < 34) g_acc[t] = 0.0;
}

// Grid (16 column-slabs, 64 row-groups), 256 threads.
// Thread owns 4 consecutive adj columns (one float4 per row), holds
// C[j..j+3][0:16] in regs as f32x2. C rows for the block's 256 i's live in SMEM.
__global__ void __launch_bounds__(256)
mod_main(const float4 * __restrict__ adj4, const float * __restrict__ C)
{
    __shared__ ulonglong2 sC[RR * 4];      // C rows of this block, f32x2-packed (16 KB)

    const int tid  = threadIdx.x;
    const int slab = blockIdx.x;           // 0..15
    const int grp  = blockIdx.y;           // 0..63
    const int i0   = grp * RR;
    const int jb   = slab * 1024 + tid * 4;

    const ulonglong2 *Cu2 = reinterpret_cast<const ulonglong2 *>(C);

    // stage C rows [i0, i0+RR) into SMEM (one row per thread)
    #pragma unroll
    for (int q = 0; q < 4; q++)
        sC[tid * 4 + q] = Cu2[(size_t)(i0 + tid) * 4 + q];

    // per-thread column C vectors in registers
    u64 c[4][8];
    #pragma unroll
    for (int t = 0; t < 4; t++) {
        #pragma unroll
        for (int q = 0; q < 4; q++) {
            ulonglong2 w = Cu2[(size_t)(jb + t) * 4 + q];
            c[t][2 * q] = w.x; c[t][2 * q + 1] = w.y;
        }
    }

    u64 dc[8], tacc[4];
    #pragma unroll
    for (int r = 0; r < 8; r++) dc[r] = 0ull;
    #pragma unroll
    for (int r = 0; r < 4; r++) tacc[r] = 0ull;
    float macc = 0.f;

    __syncthreads();

    const float4 *arow = adj4 + (size_t)i0 * 4096 + (size_t)(slab * 256 + tid);

    // prefetch ring, depth 8 (branchless wrap keeps addresses in-bounds)
    float4 a[8];
    #pragma unroll
    for (int u = 0; u < 8; u++) a[u] = arow[(size_t)u * 4096];

    for (int ii = 0; ii < RR; ii += 8) {
        #pragma unroll
        for (int u = 0; u < 8; u++) {
            float4 av = a[u];
            int nxt = (ii + 8 + u) & (RR - 1);
            a[u] = arow[(size_t)nxt * 4096];

            const int i = ii + u;
            u64 ci[8];
            #pragma unroll
            for (int q = 0; q < 4; q++) {
                ulonglong2 w = sC[i * 4 + q];
                ci[2 * q] = w.x; ci[2 * q + 1] = w.y;
            }

            u64 ax = pk2(av.x, av.x), ay = pk2(av.y, av.y);
            u64 az = pk2(av.z, av.z), aw = pk2(av.w, av.w);

            u64 p[8];
            #pragma unroll
            for (int r = 0; r < 8; r++) p[r] = mul2(ax, c[0][r]);
            #pragma unroll
            for (int r = 0; r < 8; r++) fma2(p[r], ay, c[1][r]);
            #pragma unroll
            for (int r = 0; r < 8; r++) fma2(p[r], az, c[2][r]);
            #pragma unroll
            for (int r = 0; r < 8; r++) fma2(p[r], aw, c[3][r]);

            #pragma unroll
            for (int r = 0; r < 8; r++) fma2(tacc[r & 3], p[r], ci[r]);

            float sv = (av.x + av.y) + (av.z + av.w);
            macc += sv;
            u64 s2 = pk2(sv, sv);
            #pragma unroll
            for (int r = 0; r < 8; r++) fma2(dc[r], s2, ci[r]);
        }
    }

    // colsum of C: computed once, by slab-0 blocks, from SMEM
    float cs[16];
    #pragma unroll
    for (int k = 0; k < 16; k++) cs[k] = 0.f;
    if (slab == 0) {
        #pragma unroll
        for (int q = 0; q < 4; q++) {
            ulonglong2 w = sC[tid * 4 + q];
            float lo, hi;
            unpk2(w.x, lo, hi); cs[4 * q + 0] = lo; cs[4 * q + 1] = hi;
            unpk2(w.y, lo, hi); cs[4 * q + 2] = lo; cs[4 * q + 3] = hi;
        }
    }

    // ---- block reduction of 34 scalars ----
    float vals[34];
    {
        float t1 = 0.f;
        #pragma unroll
        for (int r = 0; r < 4; r++) { float lo, hi; unpk2(tacc[r], lo, hi); t1 += lo + hi; }
        vals[0] = t1;
        vals[1] = macc;
        #pragma unroll
        for (int r = 0; r < 8; r++) {
            float lo, hi; unpk2(dc[r], lo, hi);
            vals[2 + 2 * r] = lo; vals[3 + 2 * r] = hi;
        }
        #pragma unroll
        for (int k = 0; k < 16; k++) vals[18 + k] = cs[k];
    }

    __syncthreads();   // sC reuse barrier (red overlays nothing, but keep ordering clean)
    __shared__ float red[8][34];
    const int lane = tid & 31, warp = tid >> 5;
    #pragma unroll
    for (int q = 0; q < 34; q++) {
        float v = vals[q];
        #pragma unroll
        for (int off = 16; off > 0; off >>= 1)
            v += __shfl_down_sync(0xFFFFFFFFu, v, off);
        if (lane == 0) red[warp][q] = v;
    }
    __syncthreads();
    if (tid < 34) {
        double s = 0.0;
        #pragma unroll
        for (int w = 0; w < 8; w++) s += (double)red[w][tid];
        atomicAdd(&g_acc[tid], s);
    }
}

__global__ void mod_final(const float * __restrict__ beta, float * __restrict__ out)
{
    if (threadIdx.x != 0) return;
    double term1 = g_acc[0];
    double sumA  = g_acc[1];
    double two_m = sumA;                 // 2m = sumA
    double dot = 0.0;
    #pragma unroll
    for (int k = 0; k < 16; k++) { double d = g_acc[2 + k]; dot += d * d; }
    double modularity_term = term1 - dot / two_m;
    double mod_loss = -modularity_term / two_m;
    double col = 0.0;
    #pragma unroll
    for (int k = 0; k < 16; k++) col += fabs(g_acc[18 + k] - 1.0);
    double collapse = (4.0 / (double)NN) * col;   // sqrt(16) = 4
    out[0] = (float)(mod_loss + (double)beta[0] * collapse);
}

extern "C" void kernel_launch(void* const* d_in, const int* in_sizes, int n_in,
                              void* d_out, int out_size)
{
    const float *C    = (const float *)d_in[0];
    const float *adj  = (const float *)d_in[2];   // d_in[1] = X (unused)
    const float *beta = (const float *)d_in[3];
    float *out = (float *)d_out;
    (void)in_sizes; (void)n_in; (void)out_size;

    init_acc<<<1, 64>>>();
    mod_main<<<dim3(16, 64), 256>>>((const float4 *)adj, C);
    mod_final<<<1, 32>>>(beta, out);
}

// round 5
// speedup vs baseline: 3.5813x; 1.0810x over previous
#include <cuda_runtime.h>
#include <cuda_bf16.h>
#include <cstdint>

// Modularity loss, single streaming pass over adj[16384,16384] f32 (1 GiB).
// Restructured accumulation:
//   acc_j[k]  = sum_i A_ij * C[i,k]      (per-thread, 4 owned columns j)
//   term1     = sum_j <acc_j, C_j>       (block epilogue)
//   dC[k]     = sum_j acc_j[k]           (block epilogue -- free)
//   sumA      = sum_ij A_ij              (macc)
//   colsum[k] = sum_i C[i,k]
// out = -(term1 - dot(dC,dC)/(2m))/(2m) + beta*(sqrt(K)/N)*sum|colsum-1|, 2m=sumA

#define NN 16384
#define RR 256          // rows per block

typedef unsigned long long u64;

__device__ __forceinline__ u64 pk2(float lo, float hi) {
    u64 r; asm("mov.b64 %0, {%1, %2};" : "=l"(r) : "f"(lo), "f"(hi)); return r;
}
__device__ __forceinline__ void unpk2(u64 v, float &lo, float &hi) {
    asm("mov.b64 {%0, %1}, %2;" : "=f"(lo), "=f"(hi) : "l"(v));
}
__device__ __forceinline__ u64 add2(u64 a, u64 b) {
    u64 d; asm("add.rn.f32x2 %0, %1, %2;" : "=l"(d) : "l"(a), "l"(b)); return d;
}
__device__ __forceinline__ void fma2(u64 &d, u64 a, u64 b) {
    asm("fma.rn.f32x2 %0, %1, %2, %0;" : "+l"(d) : "l"(a), "l"(b));
}

// [0]=term1, [1]=sumA, [2..17]=dC, [18..33]=colsum
__device__ double g_acc[34];

__global__ void init_acc() {
    int t = threadIdx.x;
    if (t < 34) g_acc[t] = 0.0;
}

// Grid (16 column-slabs, 64 row-groups), 256 threads.
// Thread owns 4 consecutive adj columns (one float4 per row). Inner loop only
// does acc_t[k] += a_t * C_i[k] (32 fma2) + macc. Folds happen in the epilogue.
__global__ void __launch_bounds__(256)
mod_main(const float4 * __restrict__ adj4, const float * __restrict__ C)
{
    __shared__ ulonglong2 sC[RR * 4];      // block's C rows, f32x2-packed (16 KB)

    const int tid  = threadIdx.x;
    const int slab = blockIdx.x;           // 0..15
    const int grp  = blockIdx.y;           // 0..63
    const int i0   = grp * RR;
    const int jb   = slab * 1024 + tid * 4;

    const ulonglong2 *Cu2 = reinterpret_cast<const ulonglong2 *>(C);

    // stage C rows [i0, i0+RR)
    #pragma unroll
    for (int q = 0; q < 4; q++)
        sC[tid * 4 + q] = Cu2[(size_t)(i0 + tid) * 4 + q];

    u64 acc[4][8];
    #pragma unroll
    for (int t = 0; t < 4; t++)
        #pragma unroll
        for (int r = 0; r < 8; r++) acc[t][r] = 0ull;
    float macc = 0.f;

    __syncthreads();

    const float4 *arow = adj4 + (size_t)i0 * 4096 + (size_t)(slab * 256 + tid);

    // prefetch ring, depth 8 (branchless wrap keeps addresses in-bounds)
    float4 a[8];
    #pragma unroll
    for (int u = 0; u < 8; u++) a[u] = arow[(size_t)u * 4096];

    for (int ii = 0; ii < RR; ii += 8) {
        #pragma unroll
        for (int u = 0; u < 8; u++) {
            float4 av = a[u];
            int nxt = (ii + 8 + u) & (RR - 1);
            a[u] = arow[(size_t)nxt * 4096];

            const int i = ii + u;
            u64 ci[8];
            #pragma unroll
            for (int q = 0; q < 4; q++) {
                ulonglong2 w = sC[i * 4 + q];
                ci[2 * q] = w.x; ci[2 * q + 1] = w.y;
            }

            u64 a0 = pk2(av.x, av.x), a1 = pk2(av.y, av.y);
            u64 a2 = pk2(av.z, av.z), a3 = pk2(av.w, av.w);

            #pragma unroll
            for (int r = 0; r < 8; r++) fma2(acc[0][r], a0, ci[r]);
            #pragma unroll
            for (int r = 0; r < 8; r++) fma2(acc[1][r], a1, ci[r]);
            #pragma unroll
            for (int r = 0; r < 8; r++) fma2(acc[2][r], a2, ci[r]);
            #pragma unroll
            for (int r = 0; r < 8; r++) fma2(acc[3][r], a3, ci[r]);

            macc += (av.x + av.y) + (av.z + av.w);
        }
    }

    // ---- epilogue: fold acc with C_j, derive dC partials ----
    // dC partial: sum over this thread's 4 columns
    u64 dcv[8];
    #pragma unroll
    for (int r = 0; r < 8; r++)
        dcv[r] = add2(add2(acc[0][r], acc[1][r]), add2(acc[2][r], acc[3][r]));

    // term1 partial: sum_t <acc_t, C_{j_t}>  (C_j rows from global, L2-resident)
    u64 t1a = 0ull, t1b = 0ull;
    #pragma unroll
    for (int t = 0; t < 4; t++) {
        #pragma unroll
        for (int q = 0; q < 4; q++) {
            ulonglong2 w = Cu2[(size_t)(jb + t) * 4 + q];
            fma2(t1a, acc[t][2 * q],     w.x);
            fma2(t1b, acc[t][2 * q + 1], w.y);
        }
    }
    u64 t1s = add2(t1a, t1b);

    // colsum of C: computed once (slab 0), from SMEM
    float cs[16];
    #pragma unroll
    for (int k = 0; k < 16; k++) cs[k] = 0.f;
    if (slab == 0) {
        #pragma unroll
        for (int q = 0; q < 4; q++) {
            ulonglong2 w = sC[tid * 4 + q];
            float lo, hi;
            unpk2(w.x, lo, hi); cs[4 * q + 0] = lo; cs[4 * q + 1] = hi;
            unpk2(w.y, lo, hi); cs[4 * q + 2] = lo; cs[4 * q + 3] = hi;
        }
    }

    // ---- block reduction of 34 scalars ----
    float vals[34];
    {
        float lo, hi;
        unpk2(t1s, lo, hi);
        vals[0] = lo + hi;
        vals[1] = macc;
        #pragma unroll
        for (int r = 0; r < 8; r++) {
            unpk2(dcv[r], lo, hi);
            vals[2 + 2 * r] = lo; vals[3 + 2 * r] = hi;
        }
        #pragma unroll
        for (int k = 0; k < 16; k++) vals[18 + k] = cs[k];
    }

    __syncthreads();
    __shared__ float red[8][34];
    const int lane = tid & 31, warp = tid >> 5;
    #pragma unroll
    for (int q = 0; q < 34; q++) {
        float v = vals[q];
        #pragma unroll
        for (int off = 16; off > 0; off >>= 1)
            v += __shfl_down_sync(0xFFFFFFFFu, v, off);
        if (lane == 0) red[warp][q] = v;
    }
    __syncthreads();
    if (tid < 34) {
        double s = 0.0;
        #pragma unroll
        for (int w = 0; w < 8; w++) s += (double)red[w][tid];
        atomicAdd(&g_acc[tid], s);
    }
}

__global__ void mod_final(const float * __restrict__ beta, float * __restrict__ out)
{
    if (threadIdx.x != 0) return;
    double term1 = g_acc[0];
    double sumA  = g_acc[1];
    double two_m = sumA;                 // 2m = sumA
    double dot = 0.0;
    #pragma unroll
    for (int k = 0; k < 16; k++) { double d = g_acc[2 + k]; dot += d * d; }
    double modularity_term = term1 - dot / two_m;
    double mod_loss = -modularity_term / two_m;
    double col = 0.0;
    #pragma unroll
    for (int k = 0; k < 16; k++) col += fabs(g_acc[18 + k] - 1.0);
    double collapse = (4.0 / (double)NN) * col;   // sqrt(16) = 4
    out[0] = (float)(mod_loss + (double)beta[0] * collapse);
}

extern "C" void kernel_launch(void* const* d_in, const int* in_sizes, int n_in,
                              void* d_out, int out_size)
{
    const float *C    = (const float *)d_in[0];
    const float *adj  = (const float *)d_in[2];   // d_in[1] = X (unused)
    const float *beta = (const float *)d_in[3];
    float *out = (float *)d_out;
    (void)in_sizes; (void)n_in; (void)out_size;

    init_acc<<<1, 64>>>();
    mod_main<<<dim3(16, 64), 256>>>((const float4 *)adj, C);
    mod_final<<<1, 32>>>(beta, out);
}

// round 6
// speedup vs baseline: 4.1149x; 1.1490x over previous
#include <cuda_runtime.h>
#include <cuda_bf16.h>
#include <cstdint>

// Modularity loss, single streaming pass over adj[16384,16384] f32 (1 GiB).
//   acc_j[k]  = sum_i A_ij * C[i,k]   (per-thread, 4 owned columns j)
//   term1     = sum_j <acc_j, C_j>    (epilogue)
//   dC[k]     = sum_j acc_j[k]        (epilogue, free)
//   sumA      = sum_ij A_ij
//   colsum[k] = sum_i C[i,k]
// out = -(term1 - dot(dC,dC)/(2m))/(2m) + beta*(sqrt(K)/N)*sum|colsum-1|, 2m=sumA
//
// adj is streamed via a 3-stage cp.async.bulk pipeline (16 rows x 4KB per
// stage) so ~128KB are in flight per SM (vs 32KB with a register ring),
// pushing the kernel from latency-bound (~3.9 TB/s) to DRAM-bound.

#define NN 16384
#define RR 256            // rows per block
#define SR 16             // rows per pipeline stage
#define NSTG 3            // pipeline stages
#define STAGE_BYTES (SR * 4096)          // 64 KB (rows of 1024 f32)
#define SMEM_A (NSTG * STAGE_BYTES)      // 196608
#define SMEM_C (RR * 64)                 // 16384 (256 rows x 16 f32)
#define SMEM_BAR (SMEM_A + SMEM_C)       // barriers offset
#define SMEM_TOTAL (SMEM_BAR + 64)

typedef unsigned long long u64;

__device__ __forceinline__ u64 pk2(float lo, float hi) {
    u64 r; asm("mov.b64 %0, {%1, %2};" : "=l"(r) : "f"(lo), "f"(hi)); return r;
}
__device__ __forceinline__ void unpk2(u64 v, float &lo, float &hi) {
    asm("mov.b64 {%0, %1}, %2;" : "=f"(lo), "=f"(hi) : "l"(v));
}
__device__ __forceinline__ u64 add2(u64 a, u64 b) {
    u64 d; asm("add.rn.f32x2 %0, %1, %2;" : "=l"(d) : "l"(a), "l"(b)); return d;
}
__device__ __forceinline__ void fma2(u64 &d, u64 a, u64 b) {
    asm("fma.rn.f32x2 %0, %1, %2, %0;" : "+l"(d) : "l"(a), "l"(b));
}

__device__ __forceinline__ void mbar_init(uint32_t bar, uint32_t cnt) {
    asm volatile("mbarrier.init.shared.b64 [%0], %1;" :: "r"(bar), "r"(cnt) : "memory");
}
__device__ __forceinline__ void mbar_expect_tx(uint32_t bar, uint32_t bytes) {
    asm volatile("mbarrier.arrive.expect_tx.shared.b64 _, [%0], %1;"
                 :: "r"(bar), "r"(bytes) : "memory");
}
__device__ __forceinline__ void mbar_wait(uint32_t bar, uint32_t parity) {
    asm volatile(
        "{\n\t"
        ".reg .pred P1;\n\t"
        "WAIT_LOOP_%=:\n\t"
        "mbarrier.try_wait.parity.acquire.cta.shared::cta.b64 P1, [%0], %1, 0x989680;\n\t"
        "@P1 bra.uni WAIT_DONE_%=;\n\t"
        "bra.uni WAIT_LOOP_%=;\n\t"
        "WAIT_DONE_%=:\n\t"
        "}"
        :: "r"(bar), "r"(parity) : "memory");
}
__device__ __forceinline__ void bulk_cp(uint32_t dst, const void *src,
                                        uint32_t bytes, uint32_t bar) {
    asm volatile(
        "cp.async.bulk.shared::cta.global.mbarrier::complete_tx::bytes [%0], [%1], %2, [%3];"
        :: "r"(dst), "l"(src), "r"(bytes), "r"(bar) : "memory");
}

// [0]=term1, [1]=sumA, [2..17]=dC, [18..33]=colsum
__device__ double g_acc[34];

// Grid (16 column-slabs, 64 row-groups), 256 threads. Thread owns 4 adj cols.
__global__ void __launch_bounds__(256)
mod_main(const float * __restrict__ adj, const float * __restrict__ C)
{
    extern __shared__ char smem[];
    float *sA = reinterpret_cast<float *>(smem);
    ulonglong2 *sC = reinterpret_cast<ulonglong2 *>(smem + SMEM_A);
    const uint32_t smem_base = (uint32_t)__cvta_generic_to_shared(smem);
    const uint32_t bar0 = smem_base + SMEM_BAR;

    const int tid  = threadIdx.x;
    const int slab = blockIdx.x;          // 0..15
    const int grp  = blockIdx.y;          // 0..63
    const int i0   = grp * RR;
    const int jb   = slab * 1024 + tid * 4;

    const ulonglong2 *Cu2 = reinterpret_cast<const ulonglong2 *>(C);

    // stage this block's C rows
    #pragma unroll
    for (int q = 0; q < 4; q++)
        sC[tid * 4 + q] = Cu2[(size_t)(i0 + tid) * 4 + q];

    if (tid == 0) {
        #pragma unroll
        for (int s = 0; s < NSTG; s++) mbar_init(bar0 + 8 * s, 1);
    }
    __syncthreads();

    // adj byte base of this block's slab: row stride 65536 B, col offset slab*4096
    const char *gbase = reinterpret_cast<const char *>(adj)
                      + ((size_t)i0 << 16) + (size_t)slab * 4096;

    // prologue: fill all stages
    if (tid == 0) {
        #pragma unroll
        for (int s = 0; s < NSTG; s++) {
            mbar_expect_tx(bar0 + 8 * s, STAGE_BYTES);
            #pragma unroll
            for (int r = 0; r < SR; r++)
                bulk_cp(smem_base + s * STAGE_BYTES + r * 4096,
                        gbase + (((size_t)(s * SR + r)) << 16), 4096,
                        bar0 + 8 * s);
        }
    }

    u64 acc[4][8];
    #pragma unroll
    for (int t = 0; t < 4; t++)
        #pragma unroll
        for (int r = 0; r < 8; r++) acc[t][r] = 0ull;
    float macc = 0.f;

    const int NT = RR / SR;               // 16 stages of work
    for (int t = 0; t < NT; t++) {
        const int slot = t % NSTG;
        const uint32_t par = (uint32_t)((t / NSTG) & 1);
        mbar_wait(bar0 + 8 * slot, par);

        const float *stg = sA + slot * (STAGE_BYTES / 4) + tid * 4;
        #pragma unroll 4
        for (int r = 0; r < SR; r++) {
            float4 av = *reinterpret_cast<const float4 *>(stg + r * 1024);

            const int i = t * SR + r;
            u64 ci[8];
            #pragma unroll
            for (int q = 0; q < 4; q++) {
                ulonglong2 w = sC[i * 4 + q];
                ci[2 * q] = w.x; ci[2 * q + 1] = w.y;
            }

            u64 a0 = pk2(av.x, av.x), a1 = pk2(av.y, av.y);
            u64 a2 = pk2(av.z, av.z), a3 = pk2(av.w, av.w);

            #pragma unroll
            for (int r2 = 0; r2 < 8; r2++) fma2(acc[0][r2], a0, ci[r2]);
            #pragma unroll
            for (int r2 = 0; r2 < 8; r2++) fma2(acc[1][r2], a1, ci[r2]);
            #pragma unroll
            for (int r2 = 0; r2 < 8; r2++) fma2(acc[2][r2], a2, ci[r2]);
            #pragma unroll
            for (int r2 = 0; r2 < 8; r2++) fma2(acc[3][r2], a3, ci[r2]);

            macc += (av.x + av.y) + (av.z + av.w);
        }

        __syncthreads();   // everyone done reading this slot
        if (tid == 0 && t + NSTG < NT) {
            const int ns = t + NSTG;
            mbar_expect_tx(bar0 + 8 * slot, STAGE_BYTES);
            #pragma unroll
            for (int r = 0; r < SR; r++)
                bulk_cp(smem_base + slot * STAGE_BYTES + r * 4096,
                        gbase + (((size_t)(ns * SR + r)) << 16), 4096,
                        bar0 + 8 * slot);
        }
    }

    // ---- epilogue ----
    u64 dcv[8];
    #pragma unroll
    for (int r = 0; r < 8; r++)
        dcv[r] = add2(add2(acc[0][r], acc[1][r]), add2(acc[2][r], acc[3][r]));

    u64 t1a = 0ull, t1b = 0ull;
    #pragma unroll
    for (int t = 0; t < 4; t++) {
        #pragma unroll
        for (int q = 0; q < 4; q++) {
            ulonglong2 w = Cu2[(size_t)(jb + t) * 4 + q];
            fma2(t1a, acc[t][2 * q],     w.x);
            fma2(t1b, acc[t][2 * q + 1], w.y);
        }
    }
    u64 t1s = add2(t1a, t1b);

    float cs[16];
    #pragma unroll
    for (int k = 0; k < 16; k++) cs[k] = 0.f;
    if (slab == 0) {
        #pragma unroll
        for (int q = 0; q < 4; q++) {
            ulonglong2 w = sC[tid * 4 + q];
            float lo, hi;
            unpk2(w.x, lo, hi); cs[4 * q + 0] = lo; cs[4 * q + 1] = hi;
            unpk2(w.y, lo, hi); cs[4 * q + 2] = lo; cs[4 * q + 3] = hi;
        }
    }

    float vals[34];
    {
        float lo, hi;
        unpk2(t1s, lo, hi);
        vals[0] = lo + hi;
        vals[1] = macc;
        #pragma unroll
        for (int r = 0; r < 8; r++) {
            unpk2(dcv[r], lo, hi);
            vals[2 + 2 * r] = lo; vals[3 + 2 * r] = hi;
        }
        #pragma unroll
        for (int k = 0; k < 16; k++) vals[18 + k] = cs[k];
    }

    __syncthreads();
    float *red = reinterpret_cast<float *>(smem);   // reuse stage smem
    const int lane = tid & 31, warp = tid >> 5;
    #pragma unroll
    for (int q = 0; q < 34; q++) {
        float v = vals[q];
        #pragma unroll
        for (int off = 16; off > 0; off >>= 1)
            v += __shfl_down_sync(0xFFFFFFFFu, v, off);
        if (lane == 0) red[warp * 34 + q] = v;
    }
    __syncthreads();
    if (tid < 34) {
        double s = 0.0;
        #pragma unroll
        for (int w = 0; w < 8; w++) s += (double)red[w * 34 + tid];
        atomicAdd(&g_acc[tid], s);
    }
}

__global__ void mod_final(const float * __restrict__ beta, float * __restrict__ out)
{
    const int tid = threadIdx.x;
    if (tid == 0) {
        double term1 = g_acc[0];
        double two_m = g_acc[1];             // 2m = sumA
        double dot = 0.0;
        #pragma unroll
        for (int k = 0; k < 16; k++) { double d = g_acc[2 + k]; dot += d * d; }
        double modularity_term = term1 - dot / two_m;
        double mod_loss = -modularity_term / two_m;
        double col = 0.0;
        #pragma unroll
        for (int k = 0; k < 16; k++) col += fabs(g_acc[18 + k] - 1.0);
        double collapse = (4.0 / (double)NN) * col;   // sqrt(16) = 4
        out[0] = (float)(mod_loss + (double)beta[0] * collapse);
    }
    __syncthreads();
    if (tid < 34) g_acc[tid] = 0.0;          // reset for next graph replay
}

extern "C" void kernel_launch(void* const* d_in, const int* in_sizes, int n_in,
                              void* d_out, int out_size)
{
    const float *C    = (const float *)d_in[0];
    const float *adj  = (const float *)d_in[2];   // d_in[1] = X (unused)
    const float *beta = (const float *)d_in[3];
    float *out = (float *)d_out;
    (void)in_sizes; (void)n_in; (void)out_size;

    static bool attr_set = false;
    if (!attr_set) {
        cudaFuncSetAttribute(mod_main,
                             cudaFuncAttributeMaxDynamicSharedMemorySize, SMEM_TOTAL);
        attr_set = true;
    }

    mod_main<<<dim3(16, 64), 256, SMEM_TOTAL>>>(adj, C);
    mod_final<<<1, 64>>>(beta, out);
}

// round 12
// speedup vs baseline: 4.4026x; 1.0699x over previous
#include <cuda_runtime.h>
#include <cuda_fp16.h>
#include <cstdint>

// Modularity loss, single streaming pass over adj[16384,16384] f32 (1 GiB).
//   acc_j[k]  = sum_i A_ij * C[i,k]   (per-thread, 4 owned columns j; fp16x2 HFMA2)
//   term1     = sum_j <acc_j, C_j>    (epilogue, fp32)
//   dC[k]     = sum_j acc_j[k]        (epilogue, free)
//   sumA      = sum_ij A_ij           (fp32 macc)
//   colsum[k] = sum_i C[i,k]
// out = -(term1 - dot(dC,dC)/(2m))/(2m) + beta*(sqrt(K)/N)*sum|colsum-1|, 2m=sumA
//
// adj streamed via 3-stage cp.async.bulk pipeline (64KB/stage, ~192KB in flight
// per SM). Inner product on HFMA2 (rt 2) instead of packed f32x2 FFMA (rt 4),
// halving the fma-pipe cost; fp16 accumulation error (~1e3 absolute on term1)
// is >3 orders below the tolerance budget.

#define NN 16384
#define RR 256            // rows per block
#define SR 16             // rows per pipeline stage
#define NSTG 3            // pipeline stages
#define STAGE_BYTES (SR * 4096)          // 64 KB
#define SMEM_A (NSTG * STAGE_BYTES)      // 196608
#define SMEM_C (RR * 32)                 // 8192 (256 rows x 8 half2)
#define SMEM_BAR (SMEM_A + SMEM_C)
#define SMEM_TOTAL (SMEM_BAR + 64)

__device__ __forceinline__ void mbar_init(uint32_t bar, uint32_t cnt) {
    asm volatile("mbarrier.init.shared.b64 [%0], %1;" :: "r"(bar), "r"(cnt) : "memory");
}
__device__ __forceinline__ void mbar_expect_tx(uint32_t bar, uint32_t bytes) {
    asm volatile("mbarrier.arrive.expect_tx.shared.b64 _, [%0], %1;"
                 :: "r"(bar), "r"(bytes) : "memory");
}
__device__ __forceinline__ void mbar_wait(uint32_t bar, uint32_t parity) {
    asm volatile(
        "{\n\t"
        ".reg .pred P1;\n\t"
        "WAIT_LOOP_%=:\n\t"
        "mbarrier.try_wait.parity.acquire.cta.shared::cta.b64 P1, [%0], %1, 0x989680;\n\t"
        "@P1 bra.uni WAIT_DONE_%=;\n\t"
        "bra.uni WAIT_LOOP_%=;\n\t"
        "WAIT_DONE_%=:\n\t"
        "}"
        :: "r"(bar), "r"(parity) : "memory");
}
__device__ __forceinline__ void bulk_cp(uint32_t dst, const void *src,
                                        uint32_t bytes, uint32_t bar) {
    asm volatile(
        "cp.async.bulk.shared::cta.global.mbarrier::complete_tx::bytes [%0], [%1], %2, [%3];"
        :: "r"(dst), "l"(src), "r"(bytes), "r"(bar) : "memory");
}

// [0]=term1, [1]=sumA, [2..17]=dC, [18..33]=colsum
__device__ double g_acc[34];

// Grid (16 column-slabs, 64 row-groups), 256 threads. Thread owns 4 adj cols.
__global__ void __launch_bounds__(256)
mod_main(const float * __restrict__ adj, const float * __restrict__ C)
{
    extern __shared__ char smem[];
    float *sA = reinterpret_cast<float *>(smem);
    __half2 *sCh = reinterpret_cast<__half2 *>(smem + SMEM_A);  // [RR * 8]
    const uint32_t smem_base = (uint32_t)__cvta_generic_to_shared(smem);
    const uint32_t bar0 = smem_base + SMEM_BAR;

    const int tid  = threadIdx.x;
    const int slab = blockIdx.x;          // 0..15
    const int grp  = blockIdx.y;          // 0..63
    const int i0   = grp * RR;
    const int jb   = slab * 1024 + tid * 4;

    const float4 *Cf4 = reinterpret_cast<const float4 *>(C);

    // stage this block's C rows as half2 (+ keep fp32 row for colsum)
    float myrow[16];
    {
        #pragma unroll
        for (int q = 0; q < 4; q++) {
            float4 w = Cf4[(size_t)(i0 + tid) * 4 + q];
            myrow[4*q+0] = w.x; myrow[4*q+1] = w.y;
            myrow[4*q+2] = w.z; myrow[4*q+3] = w.w;
        }
        #pragma unroll
        for (int r = 0; r < 8; r++)
            sCh[tid * 8 + r] = __floats2half2_rn(myrow[2*r], myrow[2*r+1]);
    }

    if (tid == 0) {
        #pragma unroll
        for (int s = 0; s < NSTG; s++) mbar_init(bar0 + 8 * s, 1);
    }
    __syncthreads();

    // adj byte base of this block's slab: row stride 65536 B, col offset slab*4096
    const char *gbase = reinterpret_cast<const char *>(adj)
                      + ((size_t)i0 << 16) + (size_t)slab * 4096;

    // prologue: fill all stages
    if (tid == 0) {
        #pragma unroll
        for (int s = 0; s < NSTG; s++) {
            mbar_expect_tx(bar0 + 8 * s, STAGE_BYTES);
            #pragma unroll
            for (int r = 0; r < SR; r++)
                bulk_cp(smem_base + s * STAGE_BYTES + r * 4096,
                        gbase + (((size_t)(s * SR + r)) << 16), 4096,
                        bar0 + 8 * s);
        }
    }

    __half2 acc[4][8];
    #pragma unroll
    for (int t = 0; t < 4; t++)
        #pragma unroll
        for (int r = 0; r < 8; r++) acc[t][r] = __floats2half2_rn(0.f, 0.f);
    float macc = 0.f;

    const int NT = RR / SR;               // 16 stages of work
    for (int t = 0; t < NT; t++) {
        const int slot = t % NSTG;
        const uint32_t par = (uint32_t)((t / NSTG) & 1);
        mbar_wait(bar0 + 8 * slot, par);

        const float *stg = sA + slot * (STAGE_BYTES / 4) + tid * 4;
        #pragma unroll 4
        for (int r = 0; r < SR; r++) {
            float4 av = *reinterpret_cast<const float4 *>(stg + r * 1024);

            const int i = t * SR + r;
            __half2 ci[8];
            #pragma unroll
            for (int q = 0; q < 8; q++) ci[q] = sCh[i * 8 + q];

            __half2 a0 = __float2half2_rn(av.x);
            __half2 a1 = __float2half2_rn(av.y);
            __half2 a2 = __float2half2_rn(av.z);
            __half2 a3 = __float2half2_rn(av.w);

            #pragma unroll
            for (int r2 = 0; r2 < 8; r2++) acc[0][r2] = __hfma2(a0, ci[r2], acc[0][r2]);
            #pragma unroll
            for (int r2 = 0; r2 < 8; r2++) acc[1][r2] = __hfma2(a1, ci[r2], acc[1][r2]);
            #pragma unroll
            for (int r2 = 0; r2 < 8; r2++) acc[2][r2] = __hfma2(a2, ci[r2], acc[2][r2]);
            #pragma unroll
            for (int r2 = 0; r2 < 8; r2++) acc[3][r2] = __hfma2(a3, ci[r2], acc[3][r2]);

            macc += (av.x + av.y) + (av.z + av.w);
        }

        __syncthreads();   // everyone done reading this slot
        if (tid == 0 && t + NSTG < NT) {
            const int ns = t + NSTG;
            mbar_expect_tx(bar0 + 8 * slot, STAGE_BYTES);
            #pragma unroll
            for (int r = 0; r < SR; r++)
                bulk_cp(smem_base + slot * STAGE_BYTES + r * 4096,
                        gbase + (((size_t)(ns * SR + r)) << 16), 4096,
                        bar0 + 8 * slot);
        }
    }

    // ---- epilogue: unpack acc to fp32 ----
    float af[4][16];
    #pragma unroll
    for (int t = 0; t < 4; t++) {
        #pragma unroll
        for (int r = 0; r < 8; r++) {
            float2 f = __half22float2(acc[t][r]);
            af[t][2 * r]     = f.x;
            af[t][2 * r + 1] = f.y;
        }
    }

    // dC partial: sum over this thread's 4 columns
    float dcv[16];
    #pragma unroll
    for (int k = 0; k < 16; k++)
        dcv[k] = (af[0][k] + af[1][k]) + (af[2][k] + af[3][k]);

    // term1 partial: sum_t <acc_t, C_{j_t}> with fp32 C_j from global (L2-hot)
    float t1 = 0.f;
    #pragma unroll
    for (int t = 0; t < 4; t++) {
        #pragma unroll
        for (int q = 0; q < 4; q++) {
            float4 w = Cf4[(size_t)(jb + t) * 4 + q];
            t1 += af[t][4*q+0] * w.x + af[t][4*q+1] * w.y
                + af[t][4*q+2] * w.z + af[t][4*q+3] * w.w;
        }
    }

    // colsum of C: computed once (slab 0), from the fp32 row kept in registers
    float cs[16];
    #pragma unroll
    for (int k = 0; k < 16; k++) cs[k] = (slab == 0) ? myrow[k] : 0.f;

    // ---- block reduction of 34 scalars ----
    float vals[34];
    vals[0] = t1;
    vals[1] = macc;
    #pragma unroll
    for (int k = 0; k < 16; k++) vals[2 + k]  = dcv[k];
    #pragma unroll
    for (int k = 0; k < 16; k++) vals[18 + k] = cs[k];

    __syncthreads();
    float *red = reinterpret_cast<float *>(smem);   // reuse stage smem
    const int lane = tid & 31, warp = tid >> 5;
    #pragma unroll
    for (int q = 0; q < 34; q++) {
        float v = vals[q];
        #pragma unroll
        for (int off = 16; off > 0; off >>= 1)
            v += __shfl_down_sync(0xFFFFFFFFu, v, off);
        if (lane == 0) red[warp * 34 + q] = v;
    }
    __syncthreads();
    if (tid < 34) {
        double s = 0.0;
        #pragma unroll
        for (int w = 0; w < 8; w++) s += (double)red[w * 34 + tid];
        atomicAdd(&g_acc[tid], s);
    }
}

__global__ void mod_final(const float * __restrict__ beta, float * __restrict__ out)
{
    const int tid = threadIdx.x;
    if (tid == 0) {
        double term1 = g_acc[0];
        double two_m = g_acc[1];             // 2m = sumA
        double dot = 0.0;
        #pragma unroll
        for (int k = 0; k < 16; k++) { double d = g_acc[2 + k]; dot += d * d; }
        double modularity_term = term1 - dot / two_m;
        double mod_loss = -modularity_term / two_m;
        double col = 0.0;
        #pragma unroll
        for (int k = 0; k < 16; k++) col += fabs(g_acc[18 + k] - 1.0);
        double collapse = (4.0 / (double)NN) * col;   // sqrt(16) = 4
        out[0] = (float)(mod_loss + (double)beta[0] * collapse);
    }
    __syncthreads();
    if (tid < 34) g_acc[tid] = 0.0;          // reset for next graph replay
}

extern "C" void kernel_launch(void* const* d_in, const int* in_sizes, int n_in,
                              void* d_out, int out_size)
{
    const float *C    = (const float *)d_in[0];
    const float *adj  = (const float *)d_in[2];   // d_in[1] = X (unused)
    const float *beta = (const float *)d_in[3];
    float *out = (float *)d_out;
    (void)in_sizes; (void)n_in; (void)out_size;

    static bool attr_set = false;
    if (!attr_set) {
        cudaFuncSetAttribute(mod_main,
                             cudaFuncAttributeMaxDynamicSharedMemorySize, SMEM_TOTAL);
        attr_set = true;
    }

    mod_main<<<dim3(16, 64), 256, SMEM_TOTAL>>>(adj, C);
    mod_final<<<1, 64>>>(beta, out);
}

// round 15
// speedup vs baseline: 4.4128x; 1.0023x over previous
#include <cuda_runtime.h>
#include <cuda_fp16.h>
#include <cstdint>

// Modularity loss, single streaming pass over adj[16384,16384] f32 (1 GiB).
//   acc_j[k]  = sum_i A_ij * C[i,k]   (per-thread, 4 owned columns j; fp16x2 HFMA2)
//   term1     = sum_j <acc_j, C_j>    (epilogue, fp32)
//   dC[k]     = sum_j acc_j[k]        (epilogue, free)
//   sumA      = sum_ij A_ij           (fp32 macc)
//   colsum[k] = sum_i C[i,k]
// out = -(term1 - dot(dC,dC)/(2m))/(2m) + beta*(sqrt(K)/N)*sum|colsum-1|, 2m=sumA
//
// adj streamed via 3-stage cp.async.bulk pipeline (64KB/stage, ~192KB in flight
// per SM). Inner product on HFMA2 (rt 2) instead of packed f32x2 FFMA (rt 4),
// halving the fma-pipe cost; fp16 accumulation error (~1e3 absolute on term1)
// is >3 orders below the tolerance budget.

#define NN 16384
#define RR 256            // rows per block
#define SR 16             // rows per pipeline stage
#define NSTG 3            // pipeline stages
#define STAGE_BYTES (SR * 4096)          // 64 KB
#define SMEM_A (NSTG * STAGE_BYTES)      // 196608
#define SMEM_C (RR * 32)                 // 8192 (256 rows x 8 half2)
#define SMEM_BAR (SMEM_A + SMEM_C)
#define SMEM_TOTAL (SMEM_BAR + 64)

__device__ __forceinline__ void mbar_init(uint32_t bar, uint32_t cnt) {
    asm volatile("mbarrier.init.shared.b64 [%0], %1;" :: "r"(bar), "r"(cnt) : "memory");
}
__device__ __forceinline__ void mbar_expect_tx(uint32_t bar, uint32_t bytes) {
    asm volatile("mbarrier.arrive.expect_tx.shared.b64 _, [%0], %1;"
                 :: "r"(bar), "r"(bytes) : "memory");
}
__device__ __forceinline__ void mbar_wait(uint32_t bar, uint32_t parity) {
    asm volatile(
        "{\n\t"
        ".reg .pred P1;\n\t"
        "WAIT_LOOP_%=:\n\t"
        "mbarrier.try_wait.parity.acquire.cta.shared::cta.b64 P1, [%0], %1, 0x989680;\n\t"
        "@P1 bra.uni WAIT_DONE_%=;\n\t"
        "bra.uni WAIT_LOOP_%=;\n\t"
        "WAIT_DONE_%=:\n\t"
        "}"
        :: "r"(bar), "r"(parity) : "memory");
}
__device__ __forceinline__ void bulk_cp(uint32_t dst, const void *src,
                                        uint32_t bytes, uint32_t bar) {
    asm volatile(
        "cp.async.bulk.shared::cta.global.mbarrier::complete_tx::bytes [%0], [%1], %2, [%3];"
        :: "r"(dst), "l"(src), "r"(bytes), "r"(bar) : "memory");
}

// [0]=term1, [1]=sumA, [2..17]=dC, [18..33]=colsum
__device__ double g_acc[34];

// Grid (16 column-slabs, 64 row-groups), 256 threads. Thread owns 4 adj cols.
__global__ void __launch_bounds__(256)
mod_main(const float * __restrict__ adj, const float * __restrict__ C)
{
    extern __shared__ char smem[];
    float *sA = reinterpret_cast<float *>(smem);
    __half2 *sCh = reinterpret_cast<__half2 *>(smem + SMEM_A);  // [RR * 8]
    const uint32_t smem_base = (uint32_t)__cvta_generic_to_shared(smem);
    const uint32_t bar0 = smem_base + SMEM_BAR;

    const int tid  = threadIdx.x;
    const int slab = blockIdx.x;          // 0..15
    const int grp  = blockIdx.y;          // 0..63
    const int i0   = grp * RR;
    const int jb   = slab * 1024 + tid * 4;

    const float4 *Cf4 = reinterpret_cast<const float4 *>(C);

    // stage this block's C rows as half2 (+ keep fp32 row for colsum)
    float myrow[16];
    {
        #pragma unroll
        for (int q = 0; q < 4; q++) {
            float4 w = Cf4[(size_t)(i0 + tid) * 4 + q];
            myrow[4*q+0] = w.x; myrow[4*q+1] = w.y;
            myrow[4*q+2] = w.z; myrow[4*q+3] = w.w;
        }
        #pragma unroll
        for (int r = 0; r < 8; r++)
            sCh[tid * 8 + r] = __floats2half2_rn(myrow[2*r], myrow[2*r+1]);
    }

    if (tid == 0) {
        #pragma unroll
        for (int s = 0; s < NSTG; s++) mbar_init(bar0 + 8 * s, 1);
    }
    __syncthreads();

    // adj byte base of this block's slab: row stride 65536 B, col offset slab*4096
    const char *gbase = reinterpret_cast<const char *>(adj)
                      + ((size_t)i0 << 16) + (size_t)slab * 4096;

    // prologue: fill all stages
    if (tid == 0) {
        #pragma unroll
        for (int s = 0; s < NSTG; s++) {
            mbar_expect_tx(bar0 + 8 * s, STAGE_BYTES);
            #pragma unroll
            for (int r = 0; r < SR; r++)
                bulk_cp(smem_base + s * STAGE_BYTES + r * 4096,
                        gbase + (((size_t)(s * SR + r)) << 16), 4096,
                        bar0 + 8 * s);
        }
    }

    __half2 acc[4][8];
    #pragma unroll
    for (int t = 0; t < 4; t++)
        #pragma unroll
        for (int r = 0; r < 8; r++) acc[t][r] = __floats2half2_rn(0.f, 0.f);
    float macc = 0.f;

    const int NT = RR / SR;               // 16 stages of work
    for (int t = 0; t < NT; t++) {
        const int slot = t % NSTG;
        const uint32_t par = (uint32_t)((t / NSTG) & 1);
        mbar_wait(bar0 + 8 * slot, par);

        const float *stg = sA + slot * (STAGE_BYTES / 4) + tid * 4;
        #pragma unroll 4
        for (int r = 0; r < SR; r++) {
            float4 av = *reinterpret_cast<const float4 *>(stg + r * 1024);

            const int i = t * SR + r;
            __half2 ci[8];
            #pragma unroll
            for (int q = 0; q < 8; q++) ci[q] = sCh[i * 8 + q];

            __half2 a0 = __float2half2_rn(av.x);
            __half2 a1 = __float2half2_rn(av.y);
            __half2 a2 = __float2half2_rn(av.z);
            __half2 a3 = __float2half2_rn(av.w);

            #pragma unroll
            for (int r2 = 0; r2 < 8; r2++) acc[0][r2] = __hfma2(a0, ci[r2], acc[0][r2]);
            #pragma unroll
            for (int r2 = 0; r2 < 8; r2++) acc[1][r2] = __hfma2(a1, ci[r2], acc[1][r2]);
            #pragma unroll
            for (int r2 = 0; r2 < 8; r2++) acc[2][r2] = __hfma2(a2, ci[r2], acc[2][r2]);
            #pragma unroll
            for (int r2 = 0; r2 < 8; r2++) acc[3][r2] = __hfma2(a3, ci[r2], acc[3][r2]);

            macc += (av.x + av.y) + (av.z + av.w);
        }

        __syncthreads();   // everyone done reading this slot
        if (tid == 0 && t + NSTG < NT) {
            const int ns = t + NSTG;
            mbar_expect_tx(bar0 + 8 * slot, STAGE_BYTES);
            #pragma unroll
            for (int r = 0; r < SR; r++)
                bulk_cp(smem_base + slot * STAGE_BYTES + r * 4096,
                        gbase + (((size_t)(ns * SR + r)) << 16), 4096,
                        bar0 + 8 * slot);
        }
    }

    // ---- epilogue: unpack acc to fp32 ----
    float af[4][16];
    #pragma unroll
    for (int t = 0; t < 4; t++) {
        #pragma unroll
        for (int r = 0; r < 8; r++) {
            float2 f = __half22float2(acc[t][r]);
            af[t][2 * r]     = f.x;
            af[t][2 * r + 1] = f.y;
        }
    }

    // dC partial: sum over this thread's 4 columns
    float dcv[16];
    #pragma unroll
    for (int k = 0; k < 16; k++)
        dcv[k] = (af[0][k] + af[1][k]) + (af[2][k] + af[3][k]);

    // term1 partial: sum_t <acc_t, C_{j_t}> with fp32 C_j from global (L2-hot)
    float t1 = 0.f;
    #pragma unroll
    for (int t = 0; t < 4; t++) {
        #pragma unroll
        for (int q = 0; q < 4; q++) {
            float4 w = Cf4[(size_t)(jb + t) * 4 + q];
            t1 += af[t][4*q+0] * w.x + af[t][4*q+1] * w.y
                + af[t][4*q+2] * w.z + af[t][4*q+3] * w.w;
        }
    }

    // colsum of C: computed once (slab 0), from the fp32 row kept in registers
    float cs[16];
    #pragma unroll
    for (int k = 0; k < 16; k++) cs[k] = (slab == 0) ? myrow[k] : 0.f;

    // ---- block reduction of 34 scalars ----
    float vals[34];
    vals[0] = t1;
    vals[1] = macc;
    #pragma unroll
    for (int k = 0; k < 16; k++) vals[2 + k]  = dcv[k];
    #pragma unroll
    for (int k = 0; k < 16; k++) vals[18 + k] = cs[k];

    __syncthreads();
    float *red = reinterpret_cast<float *>(smem);   // reuse stage smem
    const int lane = tid & 31, warp = tid >> 5;
    #pragma unroll
    for (int q = 0; q < 34; q++) {
        float v = vals[q];
        #pragma unroll
        for (int off = 16; off > 0; off >>= 1)
            v += __shfl_down_sync(0xFFFFFFFFu, v, off);
        if (lane == 0) red[warp * 34 + q] = v;
    }
    __syncthreads();
    if (tid < 34) {
        double s = 0.0;
        #pragma unroll
        for (int w = 0; w < 8; w++) s += (double)red[w * 34 + tid];
        atomicAdd(&g_acc[tid], s);
    }
}

__global__ void mod_final(const float * __restrict__ beta, float * __restrict__ out)
{
    const int tid = threadIdx.x;
    if (tid == 0) {
        double term1 = g_acc[0];
        double two_m = g_acc[1];             // 2m = sumA
        double dot = 0.0;
        #pragma unroll
        for (int k = 0; k < 16; k++) { double d = g_acc[2 + k]; dot += d * d; }
        double modularity_term = term1 - dot / two_m;
        double mod_loss = -modularity_term / two_m;
        double col = 0.0;
        #pragma unroll
        for (int k = 0; k < 16; k++) col += fabs(g_acc[18 + k] - 1.0);
        double collapse = (4.0 / (double)NN) * col;   // sqrt(16) = 4
        out[0] = (float)(mod_loss + (double)beta[0] * collapse);
    }
    __syncthreads();
    if (tid < 34) g_acc[tid] = 0.0;          // reset for next graph replay
}

extern "C" void kernel_launch(void* const* d_in, const int* in_sizes, int n_in,
                              void* d_out, int out_size)
{
    const float *C    = (const float *)d_in[0];
    const float *adj  = (const float *)d_in[2];   // d_in[1] = X (unused)
    const float *beta = (const float *)d_in[3];
    float *out = (float *)d_out;
    (void)in_sizes; (void)n_in; (void)out_size;

    static bool attr_set = false;
    if (!attr_set) {
        cudaFuncSetAttribute(mod_main,
                             cudaFuncAttributeMaxDynamicSharedMemorySize, SMEM_TOTAL);
        attr_set = true;
    }

    mod_main<<<dim3(16, 64), 256, SMEM_TOTAL>>>(adj, C);
    mod_final<<<1, 64>>>(beta, out);
}

// round 16
// speedup vs baseline: 4.4147x; 1.0004x over previous
#include <cuda_runtime.h>
#include <cuda_fp16.h>
#include <cstdint>

// Modularity loss, single streaming pass over adj[16384,16384] f32 (1 GiB).
//   acc_j[k]  = sum_i A_ij * C[i,k]   (per-thread, 4 owned columns j; fp16x2 HFMA2)
//   term1     = sum_j <acc_j, C_j>    (epilogue, fp32)
//   dC[k]     = sum_j acc_j[k]        (epilogue, free)
//   sumA      = sum_ij A_ij           (fp32 macc)
//   colsum[k] = sum_i C[i,k]
// out = -(term1 - dot(dC,dC)/(2m))/(2m) + beta*(sqrt(K)/N)*sum|colsum-1|, 2m=sumA
//
// adj streamed via 3-stage cp.async.bulk pipeline (64KB/stage, ~192KB in flight
// per SM). Inner product on HFMA2 (rt 2) instead of packed f32x2 FFMA (rt 4),
// halving the fma-pipe cost; fp16 accumulation error (~1e3 absolute on term1)
// is >3 orders below the tolerance budget.

#define NN 16384
#define RR 256            // rows per block
#define SR 16             // rows per pipeline stage
#define NSTG 3            // pipeline stages
#define STAGE_BYTES (SR * 4096)          // 64 KB
#define SMEM_A (NSTG * STAGE_BYTES)      // 196608
#define SMEM_C (RR * 32)                 // 8192 (256 rows x 8 half2)
#define SMEM_BAR (SMEM_A + SMEM_C)
#define SMEM_TOTAL (SMEM_BAR + 64)

__device__ __forceinline__ void mbar_init(uint32_t bar, uint32_t cnt) {
    asm volatile("mbarrier.init.shared.b64 [%0], %1;" :: "r"(bar), "r"(cnt) : "memory");
}
__device__ __forceinline__ void mbar_expect_tx(uint32_t bar, uint32_t bytes) {
    asm volatile("mbarrier.arrive.expect_tx.shared.b64 _, [%0], %1;"
                 :: "r"(bar), "r"(bytes) : "memory");
}
__device__ __forceinline__ void mbar_wait(uint32_t bar, uint32_t parity) {
    asm volatile(
        "{\n\t"
        ".reg .pred P1;\n\t"
        "WAIT_LOOP_%=:\n\t"
        "mbarrier.try_wait.parity.acquire.cta.shared::cta.b64 P1, [%0], %1, 0x989680;\n\t"
        "@P1 bra.uni WAIT_DONE_%=;\n\t"
        "bra.uni WAIT_LOOP_%=;\n\t"
        "WAIT_DONE_%=:\n\t"
        "}"
        :: "r"(bar), "r"(parity) : "memory");
}
__device__ __forceinline__ void bulk_cp(uint32_t dst, const void *src,
                                        uint32_t bytes, uint32_t bar) {
    asm volatile(
        "cp.async.bulk.shared::cta.global.mbarrier::complete_tx::bytes [%0], [%1], %2, [%3];"
        :: "r"(dst), "l"(src), "r"(bytes), "r"(bar) : "memory");
}

// [0]=term1, [1]=sumA, [2..17]=dC, [18..33]=colsum
__device__ double g_acc[34];

// Grid (16 column-slabs, 64 row-groups), 256 threads. Thread owns 4 adj cols.
__global__ void __launch_bounds__(256)
mod_main(const float * __restrict__ adj, const float * __restrict__ C)
{
    extern __shared__ char smem[];
    float *sA = reinterpret_cast<float *>(smem);
    __half2 *sCh = reinterpret_cast<__half2 *>(smem + SMEM_A);  // [RR * 8]
    const uint32_t smem_base = (uint32_t)__cvta_generic_to_shared(smem);
    const uint32_t bar0 = smem_base + SMEM_BAR;

    const int tid  = threadIdx.x;
    const int slab = blockIdx.x;          // 0..15
    const int grp  = blockIdx.y;          // 0..63
    const int i0   = grp * RR;
    const int jb   = slab * 1024 + tid * 4;

    const float4 *Cf4 = reinterpret_cast<const float4 *>(C);

    // stage this block's C rows as half2 (+ keep fp32 row for colsum)
    float myrow[16];
    {
        #pragma unroll
        for (int q = 0; q < 4; q++) {
            float4 w = Cf4[(size_t)(i0 + tid) * 4 + q];
            myrow[4*q+0] = w.x; myrow[4*q+1] = w.y;
            myrow[4*q+2] = w.z; myrow[4*q+3] = w.w;
        }
        #pragma unroll
        for (int r = 0; r < 8; r++)
            sCh[tid * 8 + r] = __floats2half2_rn(myrow[2*r], myrow[2*r+1]);
    }

    if (tid == 0) {
        #pragma unroll
        for (int s = 0; s < NSTG; s++) mbar_init(bar0 + 8 * s, 1);
    }
    __syncthreads();

    // adj byte base of this block's slab: row stride 65536 B, col offset slab*4096
    const char *gbase = reinterpret_cast<const char *>(adj)
                      + ((size_t)i0 << 16) + (size_t)slab * 4096;

    // prologue: fill all stages
    if (tid == 0) {
        #pragma unroll
        for (int s = 0; s < NSTG; s++) {
            mbar_expect_tx(bar0 + 8 * s, STAGE_BYTES);
            #pragma unroll
            for (int r = 0; r < SR; r++)
                bulk_cp(smem_base + s * STAGE_BYTES + r * 4096,
                        gbase + (((size_t)(s * SR + r)) << 16), 4096,
                        bar0 + 8 * s);
        }
    }

    __half2 acc[4][8];
    #pragma unroll
    for (int t = 0; t < 4; t++)
        #pragma unroll
        for (int r = 0; r < 8; r++) acc[t][r] = __floats2half2_rn(0.f, 0.f);
    float macc = 0.f;

    const int NT = RR / SR;               // 16 stages of work
    for (int t = 0; t < NT; t++) {
        const int slot = t % NSTG;
        const uint32_t par = (uint32_t)((t / NSTG) & 1);
        mbar_wait(bar0 + 8 * slot, par);

        const float *stg = sA + slot * (STAGE_BYTES / 4) + tid * 4;
        #pragma unroll 4
        for (int r = 0; r < SR; r++) {
            float4 av = *reinterpret_cast<const float4 *>(stg + r * 1024);

            const int i = t * SR + r;
            __half2 ci[8];
            #pragma unroll
            for (int q = 0; q < 8; q++) ci[q] = sCh[i * 8 + q];

            __half2 a0 = __float2half2_rn(av.x);
            __half2 a1 = __float2half2_rn(av.y);
            __half2 a2 = __float2half2_rn(av.z);
            __half2 a3 = __float2half2_rn(av.w);

            #pragma unroll
            for (int r2 = 0; r2 < 8; r2++) acc[0][r2] = __hfma2(a0, ci[r2], acc[0][r2]);
            #pragma unroll
            for (int r2 = 0; r2 < 8; r2++) acc[1][r2] = __hfma2(a1, ci[r2], acc[1][r2]);
            #pragma unroll
            for (int r2 = 0; r2 < 8; r2++) acc[2][r2] = __hfma2(a2, ci[r2], acc[2][r2]);
            #pragma unroll
            for (int r2 = 0; r2 < 8; r2++) acc[3][r2] = __hfma2(a3, ci[r2], acc[3][r2]);

            macc += (av.x + av.y) + (av.z + av.w);
        }

        __syncthreads();   // everyone done reading this slot
        if (tid == 0 && t + NSTG < NT) {
            const int ns = t + NSTG;
            mbar_expect_tx(bar0 + 8 * slot, STAGE_BYTES);
            #pragma unroll
            for (int r = 0; r < SR; r++)
                bulk_cp(smem_base + slot * STAGE_BYTES + r * 4096,
                        gbase + (((size_t)(ns * SR + r)) << 16), 4096,
                        bar0 + 8 * slot);
        }
    }

    // ---- epilogue: unpack acc to fp32 ----
    float af[4][16];
    #pragma unroll
    for (int t = 0; t < 4; t++) {
        #pragma unroll
        for (int r = 0; r < 8; r++) {
            float2 f = __half22float2(acc[t][r]);
            af[t][2 * r]     = f.x;
            af[t][2 * r + 1] = f.y;
        }
    }

    // dC partial: sum over this thread's 4 columns
    float dcv[16];
    #pragma unroll
    for (int k = 0; k < 16; k++)
        dcv[k] = (af[0][k] + af[1][k]) + (af[2][k] + af[3][k]);

    // term1 partial: sum_t <acc_t, C_{j_t}> with fp32 C_j from global (L2-hot)
    float t1 = 0.f;
    #pragma unroll
    for (int t = 0; t < 4; t++) {
        #pragma unroll
        for (int q = 0; q < 4; q++) {
            float4 w = Cf4[(size_t)(jb + t) * 4 + q];
            t1 += af[t][4*q+0] * w.x + af[t][4*q+1] * w.y
                + af[t][4*q+2] * w.z + af[t][4*q+3] * w.w;
        }
    }

    // colsum of C: computed once (slab 0), from the fp32 row kept in registers
    float cs[16];
    #pragma unroll
    for (int k = 0; k < 16; k++) cs[k] = (slab == 0) ? myrow[k] : 0.f;

    // ---- block reduction of 34 scalars ----
    float vals[34];
    vals[0] = t1;
    vals[1] = macc;
    #pragma unroll
    for (int k = 0; k < 16; k++) vals[2 + k]  = dcv[k];
    #pragma unroll
    for (int k = 0; k < 16; k++) vals[18 + k] = cs[k];

    __syncthreads();
    float *red = reinterpret_cast<float *>(smem);   // reuse stage smem
    const int lane = tid & 31, warp = tid >> 5;
    #pragma unroll
    for (int q = 0; q < 34; q++) {
        float v = vals[q];
        #pragma unroll
        for (int off = 16; off > 0; off >>= 1)
            v += __shfl_down_sync(0xFFFFFFFFu, v, off);
        if (lane == 0) red[warp * 34 + q] = v;
    }
    __syncthreads();
    if (tid < 34) {
        double s = 0.0;
        #pragma unroll
        for (int w = 0; w < 8; w++) s += (double)red[w * 34 + tid];
        atomicAdd(&g_acc[tid], s);
    }
}

__global__ void mod_final(const float * __restrict__ beta, float * __restrict__ out)
{
    const int tid = threadIdx.x;
    if (tid == 0) {
        double term1 = g_acc[0];
        double two_m = g_acc[1];             // 2m = sumA
        double dot = 0.0;
        #pragma unroll
        for (int k = 0; k < 16; k++) { double d = g_acc[2 + k]; dot += d * d; }
        double modularity_term = term1 - dot / two_m;
        double mod_loss = -modularity_term / two_m;
        double col = 0.0;
        #pragma unroll
        for (int k = 0; k < 16; k++) col += fabs(g_acc[18 + k] - 1.0);
        double collapse = (4.0 / (double)NN) * col;   // sqrt(16) = 4
        out[0] = (float)(mod_loss + (double)beta[0] * collapse);
    }
    __syncthreads();
    if (tid < 34) g_acc[tid] = 0.0;          // reset for next graph replay
}

extern "C" void kernel_launch(void* const* d_in, const int* in_sizes, int n_in,
                              void* d_out, int out_size)
{
    const float *C    = (const float *)d_in[0];
    const float *adj  = (const float *)d_in[2];   // d_in[1] = X (unused)
    const float *beta = (const float *)d_in[3];
    float *out = (float *)d_out;
    (void)in_sizes; (void)n_in; (void)out_size;

    static bool attr_set = false;
    if (!attr_set) {
        cudaFuncSetAttribute(mod_main,
                             cudaFuncAttributeMaxDynamicSharedMemorySize, SMEM_TOTAL);
        attr_set = true;
    }

    mod_main<<<dim3(16, 64), 256, SMEM_TOTAL>>>(adj, C);
    mod_final<<<1, 64>>>(beta, out);
}

// round 17
// speedup vs baseline: 4.4154x; 1.0001x over previous
#include <cuda_runtime.h>
#include <cuda_fp16.h>
#include <cstdint>

// Modularity loss, single streaming pass over adj[16384,16384] f32 (1 GiB).
//   acc_j[k]  = sum_i A_ij * C[i,k]   (per-thread, 4 owned columns j; fp16x2 HFMA2)
//   term1     = sum_j <acc_j, C_j>    (epilogue, fp32)
//   dC[k]     = sum_j acc_j[k]        (epilogue, free)
//   sumA      = sum_ij A_ij           (fp32 macc)
//   colsum[k] = sum_i C[i,k]
// out = -(term1 - dot(dC,dC)/(2m))/(2m) + beta*(sqrt(K)/N)*sum|colsum-1|, 2m=sumA
//
// adj streamed via 3-stage cp.async.bulk pipeline (64KB/stage, ~192KB in flight
// per SM). Inner product on HFMA2 (rt 2) instead of packed f32x2 FFMA (rt 4),
// halving the fma-pipe cost; fp16 accumulation error (~1e3 absolute on term1)
// is >3 orders below the tolerance budget.

#define NN 16384
#define RR 256            // rows per block
#define SR 16             // rows per pipeline stage
#define NSTG 3            // pipeline stages
#define STAGE_BYTES (SR * 4096)          // 64 KB
#define SMEM_A (NSTG * STAGE_BYTES)      // 196608
#define SMEM_C (RR * 32)                 // 8192 (256 rows x 8 half2)
#define SMEM_BAR (SMEM_A + SMEM_C)
#define SMEM_TOTAL (SMEM_BAR + 64)

__device__ __forceinline__ void mbar_init(uint32_t bar, uint32_t cnt) {
    asm volatile("mbarrier.init.shared.b64 [%0], %1;" :: "r"(bar), "r"(cnt) : "memory");
}
__device__ __forceinline__ void mbar_expect_tx(uint32_t bar, uint32_t bytes) {
    asm volatile("mbarrier.arrive.expect_tx.shared.b64 _, [%0], %1;"
                 :: "r"(bar), "r"(bytes) : "memory");
}
__device__ __forceinline__ void mbar_wait(uint32_t bar, uint32_t parity) {
    asm volatile(
        "{\n\t"
        ".reg .pred P1;\n\t"
        "WAIT_LOOP_%=:\n\t"
        "mbarrier.try_wait.parity.acquire.cta.shared::cta.b64 P1, [%0], %1, 0x989680;\n\t"
        "@P1 bra.uni WAIT_DONE_%=;\n\t"
        "bra.uni WAIT_LOOP_%=;\n\t"
        "WAIT_DONE_%=:\n\t"
        "}"
        :: "r"(bar), "r"(parity) : "memory");
}
__device__ __forceinline__ void bulk_cp(uint32_t dst, const void *src,
                                        uint32_t bytes, uint32_t bar) {
    asm volatile(
        "cp.async.bulk.shared::cta.global.mbarrier::complete_tx::bytes [%0], [%1], %2, [%3];"
        :: "r"(dst), "l"(src), "r"(bytes), "r"(bar) : "memory");
}

// [0]=term1, [1]=sumA, [2..17]=dC, [18..33]=colsum
__device__ double g_acc[34];

// Grid (16 column-slabs, 64 row-groups), 256 threads. Thread owns 4 adj cols.
__global__ void __launch_bounds__(256)
mod_main(const float * __restrict__ adj, const float * __restrict__ C)
{
    extern __shared__ char smem[];
    float *sA = reinterpret_cast<float *>(smem);
    __half2 *sCh = reinterpret_cast<__half2 *>(smem + SMEM_A);  // [RR * 8]
    const uint32_t smem_base = (uint32_t)__cvta_generic_to_shared(smem);
    const uint32_t bar0 = smem_base + SMEM_BAR;

    const int tid  = threadIdx.x;
    const int slab = blockIdx.x;          // 0..15
    const int grp  = blockIdx.y;          // 0..63
    const int i0   = grp * RR;
    const int jb   = slab * 1024 + tid * 4;

    const float4 *Cf4 = reinterpret_cast<const float4 *>(C);

    // stage this block's C rows as half2 (+ keep fp32 row for colsum)
    float myrow[16];
    {
        #pragma unroll
        for (int q = 0; q < 4; q++) {
            float4 w = Cf4[(size_t)(i0 + tid) * 4 + q];
            myrow[4*q+0] = w.x; myrow[4*q+1] = w.y;
            myrow[4*q+2] = w.z; myrow[4*q+3] = w.w;
        }
        #pragma unroll
        for (int r = 0; r < 8; r++)
            sCh[tid * 8 + r] = __floats2half2_rn(myrow[2*r], myrow[2*r+1]);
    }

    if (tid == 0) {
        #pragma unroll
        for (int s = 0; s < NSTG; s++) mbar_init(bar0 + 8 * s, 1);
    }
    __syncthreads();

    // adj byte base of this block's slab: row stride 65536 B, col offset slab*4096
    const char *gbase = reinterpret_cast<const char *>(adj)
                      + ((size_t)i0 << 16) + (size_t)slab * 4096;

    // prologue: fill all stages
    if (tid == 0) {
        #pragma unroll
        for (int s = 0; s < NSTG; s++) {
            mbar_expect_tx(bar0 + 8 * s, STAGE_BYTES);
            #pragma unroll
            for (int r = 0; r < SR; r++)
                bulk_cp(smem_base + s * STAGE_BYTES + r * 4096,
                        gbase + (((size_t)(s * SR + r)) << 16), 4096,
                        bar0 + 8 * s);
        }
    }

    __half2 acc[4][8];
    #pragma unroll
    for (int t = 0; t < 4; t++)
        #pragma unroll
        for (int r = 0; r < 8; r++) acc[t][r] = __floats2half2_rn(0.f, 0.f);
    float macc = 0.f;

    const int NT = RR / SR;               // 16 stages of work
    for (int t = 0; t < NT; t++) {
        const int slot = t % NSTG;
        const uint32_t par = (uint32_t)((t / NSTG) & 1);
        mbar_wait(bar0 + 8 * slot, par);

        const float *stg = sA + slot * (STAGE_BYTES / 4) + tid * 4;
        #pragma unroll 4
        for (int r = 0; r < SR; r++) {
            float4 av = *reinterpret_cast<const float4 *>(stg + r * 1024);

            const int i = t * SR + r;
            __half2 ci[8];
            #pragma unroll
            for (int q = 0; q < 8; q++) ci[q] = sCh[i * 8 + q];

            __half2 a0 = __float2half2_rn(av.x);
            __half2 a1 = __float2half2_rn(av.y);
            __half2 a2 = __float2half2_rn(av.z);
            __half2 a3 = __float2half2_rn(av.w);

            #pragma unroll
            for (int r2 = 0; r2 < 8; r2++) acc[0][r2] = __hfma2(a0, ci[r2], acc[0][r2]);
            #pragma unroll
            for (int r2 = 0; r2 < 8; r2++) acc[1][r2] = __hfma2(a1, ci[r2], acc[1][r2]);
            #pragma unroll
            for (int r2 = 0; r2 < 8; r2++) acc[2][r2] = __hfma2(a2, ci[r2], acc[2][r2]);
            #pragma unroll
            for (int r2 = 0; r2 < 8; r2++) acc[3][r2] = __hfma2(a3, ci[r2], acc[3][r2]);

            macc += (av.x + av.y) + (av.z + av.w);
        }

        __syncthreads();   // everyone done reading this slot
        if (tid == 0 && t + NSTG < NT) {
            const int ns = t + NSTG;
            mbar_expect_tx(bar0 + 8 * slot, STAGE_BYTES);
            #pragma unroll
            for (int r = 0; r < SR; r++)
                bulk_cp(smem_base + slot * STAGE_BYTES + r * 4096,
                        gbase + (((size_t)(ns * SR + r)) << 16), 4096,
                        bar0 + 8 * slot);
        }
    }

    // ---- epilogue: unpack acc to fp32 ----
    float af[4][16];
    #pragma unroll
    for (int t = 0; t < 4; t++) {
        #pragma unroll
        for (int r = 0; r < 8; r++) {
            float2 f = __half22float2(acc[t][r]);
            af[t][2 * r]     = f.x;
            af[t][2 * r + 1] = f.y;
        }
    }

    // dC partial: sum over this thread's 4 columns
    float dcv[16];
    #pragma unroll
    for (int k = 0; k < 16; k++)
        dcv[k] = (af[0][k] + af[1][k]) + (af[2][k] + af[3][k]);

    // term1 partial: sum_t <acc_t, C_{j_t}> with fp32 C_j from global (L2-hot)
    float t1 = 0.f;
    #pragma unroll
    for (int t = 0; t < 4; t++) {
        #pragma unroll
        for (int q = 0; q < 4; q++) {
            float4 w = Cf4[(size_t)(jb + t) * 4 + q];
            t1 += af[t][4*q+0] * w.x + af[t][4*q+1] * w.y
                + af[t][4*q+2] * w.z + af[t][4*q+3] * w.w;
        }
    }

    // colsum of C: computed once (slab 0), from the fp32 row kept in registers
    float cs[16];
    #pragma unroll
    for (int k = 0; k < 16; k++) cs[k] = (slab == 0) ? myrow[k] : 0.f;

    // ---- block reduction of 34 scalars ----
    float vals[34];
    vals[0] = t1;
    vals[1] = macc;
    #pragma unroll
    for (int k = 0; k < 16; k++) vals[2 + k]  = dcv[k];
    #pragma unroll
    for (int k = 0; k < 16; k++) vals[18 + k] = cs[k];

    __syncthreads();
    float *red = reinterpret_cast<float *>(smem);   // reuse stage smem
    const int lane = tid & 31, warp = tid >> 5;
    #pragma unroll
    for (int q = 0; q < 34; q++) {
        float v = vals[q];
        #pragma unroll
        for (int off = 16; off > 0; off >>= 1)
            v += __shfl_down_sync(0xFFFFFFFFu, v, off);
        if (lane == 0) red[warp * 34 + q] = v;
    }
    __syncthreads();
    if (tid < 34) {
        double s = 0.0;
        #pragma unroll
        for (int w = 0; w < 8; w++) s += (double)red[w * 34 + tid];
        atomicAdd(&g_acc[tid], s);
    }
}

__global__ void mod_final(const float * __restrict__ beta, float * __restrict__ out)
{
    const int tid = threadIdx.x;
    if (tid == 0) {
        double term1 = g_acc[0];
        double two_m = g_acc[1];             // 2m = sumA
        double dot = 0.0;
        #pragma unroll
        for (int k = 0; k < 16; k++) { double d = g_acc[2 + k]; dot += d * d; }
        double modularity_term = term1 - dot / two_m;
        double mod_loss = -modularity_term / two_m;
        double col = 0.0;
        #pragma unroll
        for (int k = 0; k < 16; k++) col += fabs(g_acc[18 + k] - 1.0);
        double collapse = (4.0 / (double)NN) * col;   // sqrt(16) = 4
        out[0] = (float)(mod_loss + (double)beta[0] * collapse);
    }
    __syncthreads();
    if (tid < 34) g_acc[tid] = 0.0;          // reset for next graph replay
}

extern "C" void kernel_launch(void* const* d_in, const int* in_sizes, int n_in,
                              void* d_out, int out_size)
{
    const float *C    = (const float *)d_in[0];
    const float *adj  = (const float *)d_in[2];   // d_in[1] = X (unused)
    const float *beta = (const float *)d_in[3];
    float *out = (float *)d_out;
    (void)in_sizes; (void)n_in; (void)out_size;

    static bool attr_set = false;
    if (!attr_set) {
        cudaFuncSetAttribute(mod_main,
                             cudaFuncAttributeMaxDynamicSharedMemorySize, SMEM_TOTAL);
        attr_set = true;
    }

    mod_main<<<dim3(16, 64), 256, SMEM_TOTAL>>>(adj, C);
    mod_final<<<1, 64>>>(beta, out);
}